// round 2
// baseline (speedup 1.0000x reference)
#include <cuda_runtime.h>

#define NN 100000
#define EE 3200000
#define HH 64
#define GGB 256
#define DOUTC 12

// ---------------- scratch (static device allocations, allowed) ----------------
__device__ float g_h[NN * HH];
__device__ float g_out0[NN * HH];
__device__ float g_Acat[NN * 320];
__device__ float g_m[NN * HH];
__device__ float g_gx[NN * 192];
__device__ float g_A1[NN * HH];
__device__ float g_I[NN * DOUTC];
__device__ float g_J[NN * DOUTC];
__device__ int g_counts[NN];
__device__ int g_rowoff[NN + 1];
__device__ int g_cursor[NN];
__device__ unsigned g_sorted[EE];

// ---------------- setup kernels ----------------

__global__ void zero_k(int* __restrict__ counts) {
    int i = blockIdx.x * blockDim.x + threadIdx.x;
    if (i < NN) counts[i] = 0;
}

// out0 = h = relu(x @ lin0_w + lin0_b), K=15
__global__ void lin0_k(const float* __restrict__ x, const float* __restrict__ w,
                       const float* __restrict__ b, float* __restrict__ h,
                       float* __restrict__ out0) {
    __shared__ float ws[15 * 64];
    __shared__ float bs[64];
    for (int i = threadIdx.x; i < 15 * 64; i += blockDim.x) ws[i] = w[i];
    if (threadIdx.x < 64) bs[threadIdx.x] = b[threadIdx.x];
    __syncthreads();
    int idx = blockIdx.x * blockDim.x + threadIdx.x;
    if (idx >= NN * 64) return;
    int n = idx >> 6, j = idx & 63;
    float s = bs[j];
    const float* xr = x + n * 15;
#pragma unroll
    for (int k = 0; k < 15; k++) s += xr[k] * ws[k * 64 + j];
    s = fmaxf(s, 0.f);
    h[idx] = s;
    out0[idx] = s;
}

__global__ void hist_k(const int* __restrict__ dst, int* __restrict__ counts) {
    int e = blockIdx.x * blockDim.x + threadIdx.x;
    if (e < EE) atomicAdd(&counts[dst[e]], 1);
}

// single-block exclusive scan over counts -> rowoff (and cursor copy)
__global__ void scan_all(const int* __restrict__ counts, int* __restrict__ rowoff,
                         int* __restrict__ cursor) {
    __shared__ int sm[1024];
    __shared__ int carry_s;
    int t = threadIdx.x;
    if (t == 0) carry_s = 0;
    __syncthreads();
    for (int base = 0; base < NN; base += 1024) {
        int i = base + t;
        int v = (i < NN) ? counts[i] : 0;
        sm[t] = v;
        __syncthreads();
        for (int off = 1; off < 1024; off <<= 1) {
            int xv = (t >= off) ? sm[t - off] : 0;
            __syncthreads();
            sm[t] += xv;
            __syncthreads();
        }
        int carry = carry_s;
        int excl = carry + sm[t] - v;
        if (i < NN) { rowoff[i] = excl; cursor[i] = excl; }
        __syncthreads();
        if (t == 1023) carry_s = carry + sm[1023];
        __syncthreads();
    }
    if (t == 0) rowoff[NN] = carry_s;
}

__global__ void fill_k(const int* __restrict__ src, const int* __restrict__ dst,
                       const int* __restrict__ typ, int* __restrict__ cursor,
                       unsigned* __restrict__ sorted) {
    int e = blockIdx.x * blockDim.x + threadIdx.x;
    if (e < EE) {
        int p = atomicAdd(&cursor[dst[e]], 1);
        sorted[p] = (unsigned)src[e] | ((unsigned)typ[e] << 17);
    }
}

// ---------------- per-step kernels ----------------

// one warp per dst node: Acat[n, t*64 + k] = sum over its type-t in-edges of h[src, k]
__global__ void agg_k(const unsigned* __restrict__ sorted, const int* __restrict__ rowoff,
                      const float* __restrict__ h, float* __restrict__ Acat) {
    int w = (int)((blockIdx.x * blockDim.x + threadIdx.x) >> 5);
    int lane = threadIdx.x & 31;
    if (w >= NN) return;
    int s = rowoff[w], e = rowoff[w + 1];
    const float2* h2 = (const float2*)h;
    float2 a0 = {0.f, 0.f}, a1 = {0.f, 0.f}, a2 = {0.f, 0.f}, a3 = {0.f, 0.f}, a4 = {0.f, 0.f};
    int i = s;
    for (; i + 2 <= e; i += 2) {
        unsigned v0 = sorted[i], v1 = sorted[i + 1];
        float2 hv0 = h2[(v0 & 0x1FFFFu) * 32u + lane];
        float2 hv1 = h2[(v1 & 0x1FFFFu) * 32u + lane];
        unsigned t0 = v0 >> 17, t1 = v1 >> 17;
        if (t0 == 0) { a0.x += hv0.x; a0.y += hv0.y; }
        else if (t0 == 1) { a1.x += hv0.x; a1.y += hv0.y; }
        else if (t0 == 2) { a2.x += hv0.x; a2.y += hv0.y; }
        else if (t0 == 3) { a3.x += hv0.x; a3.y += hv0.y; }
        else { a4.x += hv0.x; a4.y += hv0.y; }
        if (t1 == 0) { a0.x += hv1.x; a0.y += hv1.y; }
        else if (t1 == 1) { a1.x += hv1.x; a1.y += hv1.y; }
        else if (t1 == 2) { a2.x += hv1.x; a2.y += hv1.y; }
        else if (t1 == 3) { a3.x += hv1.x; a3.y += hv1.y; }
        else { a4.x += hv1.x; a4.y += hv1.y; }
    }
    if (i < e) {
        unsigned v0 = sorted[i];
        float2 hv0 = h2[(v0 & 0x1FFFFu) * 32u + lane];
        unsigned t0 = v0 >> 17;
        if (t0 == 0) { a0.x += hv0.x; a0.y += hv0.y; }
        else if (t0 == 1) { a1.x += hv0.x; a1.y += hv0.y; }
        else if (t0 == 2) { a2.x += hv0.x; a2.y += hv0.y; }
        else if (t0 == 3) { a3.x += hv0.x; a3.y += hv0.y; }
        else { a4.x += hv0.x; a4.y += hv0.y; }
    }
    float2* A2 = (float2*)(Acat + (size_t)w * 320);
    A2[lane] = a0;
    A2[32 + lane] = a1;
    A2[64 + lane] = a2;
    A2[96 + lane] = a3;
    A2[128 + lane] = a4;
}

// m[M,64] = relu( (Acat[M,320] @ W[320,64]) * inv_deg + bias ), W = edge_embed viewed [320,64]
__global__ void __launch_bounds__(256, 2)
conv_gemm(const float* __restrict__ A, const float* __restrict__ B,
          const float* __restrict__ bias, const int* __restrict__ counts,
          float* __restrict__ C, int M) {
    __shared__ float As[8][128];
    __shared__ float Bs[8][64];
    int tid = threadIdx.x;
    int tx = tid & 15, ty = tid >> 4;
    int m0 = blockIdx.x * 128;

    float acc[8][4];
#pragma unroll
    for (int i = 0; i < 8; i++)
#pragma unroll
        for (int j = 0; j < 4; j++) acc[i][j] = 0.f;

    int arow = tid >> 1;
    int akoff = (tid & 1) * 4;

    for (int kc = 0; kc < 320; kc += 8) {
        float4 av = make_float4(0.f, 0.f, 0.f, 0.f);
        int gr = m0 + arow;
        if (gr < M) av = *(const float4*)(A + (size_t)gr * 320 + kc + akoff);
        As[akoff + 0][arow] = av.x;
        As[akoff + 1][arow] = av.y;
        As[akoff + 2][arow] = av.z;
        As[akoff + 3][arow] = av.w;
        if (tid < 128) {
            int k = tid >> 4;
            int qq = (tid & 15) * 4;
            *(float4*)&Bs[k][qq] = *(const float4*)(B + (size_t)(kc + k) * 64 + qq);
        }
        __syncthreads();
#pragma unroll
        for (int k = 0; k < 8; k++) {
            float4 a0 = *(float4*)&As[k][ty * 8];
            float4 a1 = *(float4*)&As[k][ty * 8 + 4];
            float4 b = *(float4*)&Bs[k][tx * 4];
            float a[8] = {a0.x, a0.y, a0.z, a0.w, a1.x, a1.y, a1.z, a1.w};
#pragma unroll
            for (int i = 0; i < 8; i++) {
                acc[i][0] += a[i] * b.x;
                acc[i][1] += a[i] * b.y;
                acc[i][2] += a[i] * b.z;
                acc[i][3] += a[i] * b.w;
            }
        }
        __syncthreads();
    }

    int qc = tx * 4;
    float4 bv = *(const float4*)(bias + qc);
#pragma unroll
    for (int i = 0; i < 8; i++) {
        int r = m0 + ty * 8 + i;
        if (r >= M) break;
        float inv = 1.f / fmaxf((float)counts[r], 1.f);
        float4 v;
        v.x = fmaxf(acc[i][0] * inv + bv.x, 0.f);
        v.y = fmaxf(acc[i][1] * inv + bv.y, 0.f);
        v.z = fmaxf(acc[i][2] * inv + bv.z, 0.f);
        v.w = fmaxf(acc[i][3] * inv + bv.w, 0.f);
        *(float4*)(C + (size_t)r * 64 + qc) = v;
    }
}

// generic GEMM: C[M,Q] = act( A[M,64] @ B[64,Q] + bias (+ Cin) ), K=64 fixed
__global__ void __launch_bounds__(256, 2)
gemm64(const float* __restrict__ A, const float* __restrict__ B,
       const float* __restrict__ bias, const float* __restrict__ Cin,
       float* __restrict__ C, int M, int Q, int act) {
    __shared__ float As[8][128];
    __shared__ float Bs[8][64];
    int tid = threadIdx.x;
    int tx = tid & 15, ty = tid >> 4;
    int m0 = blockIdx.y * 128, q0 = blockIdx.x * 64;

    float acc[8][4];
#pragma unroll
    for (int i = 0; i < 8; i++)
#pragma unroll
        for (int j = 0; j < 4; j++) acc[i][j] = 0.f;

    int arow = tid >> 1;
    int akoff = (tid & 1) * 4;

    for (int kc = 0; kc < 64; kc += 8) {
        float4 av = make_float4(0.f, 0.f, 0.f, 0.f);
        int gr = m0 + arow;
        if (gr < M) av = *(const float4*)(A + (size_t)gr * 64 + kc + akoff);
        As[akoff + 0][arow] = av.x;
        As[akoff + 1][arow] = av.y;
        As[akoff + 2][arow] = av.z;
        As[akoff + 3][arow] = av.w;
        if (tid < 128) {
            int k = tid >> 4;
            int qq = (tid & 15) * 4;
            float4 bv = make_float4(0.f, 0.f, 0.f, 0.f);
            if (q0 + qq < Q) bv = *(const float4*)(B + (size_t)(kc + k) * Q + q0 + qq);
            *(float4*)&Bs[k][qq] = bv;
        }
        __syncthreads();
#pragma unroll
        for (int k = 0; k < 8; k++) {
            float4 a0 = *(float4*)&As[k][ty * 8];
            float4 a1 = *(float4*)&As[k][ty * 8 + 4];
            float4 b = *(float4*)&Bs[k][tx * 4];
            float a[8] = {a0.x, a0.y, a0.z, a0.w, a1.x, a1.y, a1.z, a1.w};
#pragma unroll
            for (int i = 0; i < 8; i++) {
                acc[i][0] += a[i] * b.x;
                acc[i][1] += a[i] * b.y;
                acc[i][2] += a[i] * b.z;
                acc[i][3] += a[i] * b.w;
            }
        }
        __syncthreads();
    }

    int qc = q0 + tx * 4;
    if (qc >= Q) return;
    float4 bv = make_float4(0.f, 0.f, 0.f, 0.f);
    if (bias) bv = *(const float4*)(bias + qc);
#pragma unroll
    for (int i = 0; i < 8; i++) {
        int r = m0 + ty * 8 + i;
        if (r >= M) break;
        float4 v;
        v.x = acc[i][0] + bv.x;
        v.y = acc[i][1] + bv.y;
        v.z = acc[i][2] + bv.z;
        v.w = acc[i][3] + bv.w;
        if (Cin) {
            float4 c = *(const float4*)(Cin + (size_t)r * Q + qc);
            v.x += c.x; v.y += c.y; v.z += c.z; v.w += c.w;
        }
        if (act == 1) {
            v.x = fmaxf(v.x, 0.f); v.y = fmaxf(v.y, 0.f);
            v.z = fmaxf(v.z, 0.f); v.w = fmaxf(v.w, 0.f);
        } else if (act == 2) {
            v.x = 1.f / (1.f + __expf(-v.x));
            v.y = 1.f / (1.f + __expf(-v.y));
            v.z = 1.f / (1.f + __expf(-v.z));
            v.w = 1.f / (1.f + __expf(-v.w));
        }
        *(float4*)(C + (size_t)r * Q + qc) = v;
    }
}

// fused: gh = h @ whh + bhh, then GRU with gx -> h updated in place.
// tile: 32 rows x 192 cols; 256 threads: tx=col(0..63), ty=row-group(0..3), 8 rows each.
__global__ void __launch_bounds__(256)
gru_fused(const float* __restrict__ h, const float* __restrict__ whh,
          const float* __restrict__ bhh, const float* __restrict__ gx,
          float* __restrict__ hout, int M) {
    __shared__ float As[8][32];
    __shared__ float Bs[8][192];
    __shared__ float bsh[192];
    int tid = threadIdx.x;
    int tx = tid & 63, ty = tid >> 6;
    int m0 = blockIdx.x * 32;
    if (tid < 192) bsh[tid] = bhh[tid];

    float acc[8][3];
#pragma unroll
    for (int i = 0; i < 8; i++) { acc[i][0] = 0.f; acc[i][1] = 0.f; acc[i][2] = 0.f; }

    for (int kc = 0; kc < 64; kc += 8) {
        if (tid < 64) {
            int arow = tid >> 1;
            int akoff = (tid & 1) * 4;
            float4 av = make_float4(0.f, 0.f, 0.f, 0.f);
            int gr = m0 + arow;
            if (gr < M) av = *(const float4*)(h + (size_t)gr * 64 + kc + akoff);
            As[akoff + 0][arow] = av.x;
            As[akoff + 1][arow] = av.y;
            As[akoff + 2][arow] = av.z;
            As[akoff + 3][arow] = av.w;
        }
        for (int i = tid; i < 384; i += 256) {
            int k = i / 48;
            int c = (i - k * 48) * 4;
            *(float4*)&Bs[k][c] = *(const float4*)(whh + (size_t)(kc + k) * 192 + c);
        }
        __syncthreads();
#pragma unroll
        for (int k = 0; k < 8; k++) {
            float b0 = Bs[k][tx], b1 = Bs[k][64 + tx], b2 = Bs[k][128 + tx];
#pragma unroll
            for (int i = 0; i < 8; i++) {
                float a = As[k][ty * 8 + i];
                acc[i][0] += a * b0;
                acc[i][1] += a * b1;
                acc[i][2] += a * b2;
            }
        }
        __syncthreads();
    }

#pragma unroll
    for (int i = 0; i < 8; i++) {
        int r = m0 + ty * 8 + i;
        if (r >= M) break;
        const float* gxp = gx + (size_t)r * 192;
        float ghr = acc[i][0] + bsh[tx];
        float ghz = acc[i][1] + bsh[64 + tx];
        float ghn = acc[i][2] + bsh[128 + tx];
        float rg = 1.f / (1.f + __expf(-(gxp[tx] + ghr)));
        float z = 1.f / (1.f + __expf(-(gxp[64 + tx] + ghz)));
        float nn = tanhf(gxp[128 + tx] + rg * ghn);
        float hv = h[(size_t)r * 64 + tx];
        hout[(size_t)r * 64 + tx] = (1.f - z) * nn + z * hv;
    }
}

// gated = I*J, scatter-add by batch
__global__ void final_k(const float* __restrict__ I, const float* __restrict__ J,
                        const int* __restrict__ batch, float* __restrict__ out) {
    int idx = blockIdx.x * blockDim.x + threadIdx.x;
    if (idx >= NN * 12) return;
    int n = idx / 12;
    int j = idx - n * 12;
    atomicAdd(&out[batch[n] * 12 + j], I[idx] * J[idx]);
}

// ---------------- launch ----------------
extern "C" void kernel_launch(void* const* d_in, const int* in_sizes, int n_in,
                              void* d_out, int out_size) {
    const float* x      = (const float*)d_in[0];
    const int*   ei     = (const int*)d_in[1];   // [2,E]: src then dst
    const int*   ea     = (const int*)d_in[2];
    const int*   batch  = (const int*)d_in[3];
    const float* lin0_w = (const float*)d_in[4];
    const float* lin0_b = (const float*)d_in[5];
    const float* ee     = (const float*)d_in[6];  // = Wstack [320,64] row-major
    const float* cbias  = (const float*)d_in[7];
    const float* wih    = (const float*)d_in[8];
    const float* whh    = (const float*)d_in[9];
    const float* bih    = (const float*)d_in[10];
    const float* bhh    = (const float*)d_in[11];
    const float* iw1    = (const float*)d_in[12];
    const float* ib1    = (const float*)d_in[13];
    const float* iw2    = (const float*)d_in[14];
    const float* ib2    = (const float*)d_in[15];
    const float* jw1    = (const float*)d_in[16];
    const float* jb1    = (const float*)d_in[17];
    const float* jw2    = (const float*)d_in[18];
    const float* jb2    = (const float*)d_in[19];
    float* out = (float*)d_out;

    float *h, *out0, *Acat, *m, *gx, *A1, *I, *J;
    int *counts, *rowoff, *cursor;
    unsigned* sorted;
    cudaGetSymbolAddress((void**)&h, g_h);
    cudaGetSymbolAddress((void**)&out0, g_out0);
    cudaGetSymbolAddress((void**)&Acat, g_Acat);
    cudaGetSymbolAddress((void**)&m, g_m);
    cudaGetSymbolAddress((void**)&gx, g_gx);
    cudaGetSymbolAddress((void**)&A1, g_A1);
    cudaGetSymbolAddress((void**)&I, g_I);
    cudaGetSymbolAddress((void**)&J, g_J);
    cudaGetSymbolAddress((void**)&counts, g_counts);
    cudaGetSymbolAddress((void**)&rowoff, g_rowoff);
    cudaGetSymbolAddress((void**)&cursor, g_cursor);
    cudaGetSymbolAddress((void**)&sorted, g_sorted);

    cudaStream_t s = 0;

    zero_k<<<(NN + 255) / 256, 256, 0, s>>>(counts);
    lin0_k<<<(NN * 64 + 255) / 256, 256, 0, s>>>(x, lin0_w, lin0_b, h, out0);
    hist_k<<<(EE + 255) / 256, 256, 0, s>>>(ei + EE, counts);
    scan_all<<<1, 1024, 0, s>>>(counts, rowoff, cursor);
    fill_k<<<(EE + 255) / 256, 256, 0, s>>>(ei, ei + EE, ea, cursor, sorted);

    dim3 g3(3, (NN + 127) / 128);
    dim3 g1(1, (NN + 127) / 128);
    int nconv = (NN + 127) / 128;
    int ngru = (NN + 31) / 32;

    for (int step = 0; step < 6; step++) {
        agg_k<<<(NN * 32 + 255) / 256, 256, 0, s>>>(sorted, rowoff, h, Acat);
        conv_gemm<<<nconv, 256, 0, s>>>(Acat, ee, cbias, counts, m, NN);
        gemm64<<<g3, 256, 0, s>>>(m, wih, bih, nullptr, gx, NN, 192, 0);
        gru_fused<<<ngru, 256, 0, s>>>(h, whh, bhh, gx, h, NN);
    }

    // readout
    gemm64<<<g1, 256, 0, s>>>(h, iw1, ib1, nullptr, A1, NN, 64, 0);             // A1 = h@iw1[0:64] + b
    gemm64<<<g1, 256, 0, s>>>(out0, iw1 + 64 * 64, nullptr, A1, A1, NN, 64, 2); // A1 = sig(A1 + out0@iw1[64:128])
    gemm64<<<g1, 256, 0, s>>>(A1, iw2, ib2, nullptr, I, NN, 12, 2);             // I = sig(A1@iw2 + b)
    gemm64<<<g1, 256, 0, s>>>(h, jw1, jb1, nullptr, m, NN, 64, 2);              // B1 = sig(h@jw1 + b), reuse m
    gemm64<<<g1, 256, 0, s>>>(m, jw2, jb2, nullptr, J, NN, 12, 0);              // J = B1@jw2 + b

    cudaMemsetAsync(out, 0, GGB * DOUTC * sizeof(float), s);
    final_k<<<(NN * 12 + 255) / 256, 256, 0, s>>>(I, J, batch, out);
}

// round 4
// speedup vs baseline: 2.2323x; 2.2323x over previous
#include <cuda_runtime.h>
#include <cuda_bf16.h>
#include <cstdint>

#define NN 100000
#define EE 3200000
#define HH 64
#define GGB 256
#define DOUTC 12

// ---------------- scratch ----------------
__device__ float g_h[NN * HH];
__device__ float g_out0[NN * HH];
__device__ float g_T[NN * 320];
__device__ float g_m[NN * HH];
__device__ float g_gx[NN * 192];
__device__ float g_gh[NN * 192];
__device__ float g_A1[NN * HH];
__device__ float g_I[NN * DOUTC];
__device__ float g_J[NN * DOUTC];
__device__ int g_counts[NN];
__device__ int g_rowoff[NN + 1];
__device__ int g_cursor[NN];
__device__ int g_bsums[128];
__device__ unsigned g_sorted[EE];
// transposed + bf16-split weights: rows 0..319 Wc^T, 320..511 wih^T, 512..703 whh^T
__device__ __nv_bfloat16 g_wthi[704 * 64];
__device__ __nv_bfloat16 g_wtlo[704 * 64];

// ---------------- mma.sync helpers (arch-neutral, sm_80+) ----------------
__device__ __forceinline__ uint32_t smem_u32(const void* p) {
    uint32_t a;
    asm("{ .reg .u64 t; cvta.to.shared.u64 t, %1; cvt.u32.u64 %0, t; }" : "=r"(a) : "l"(p));
    return a;
}
__device__ __forceinline__ void ldsm4(uint32_t* r, uint32_t addr) {
    asm volatile("ldmatrix.sync.aligned.m8n8.x4.shared.b16 {%0,%1,%2,%3}, [%4];"
                 : "=r"(r[0]), "=r"(r[1]), "=r"(r[2]), "=r"(r[3]) : "r"(addr));
}
__device__ __forceinline__ void ldsm2(uint32_t* r, uint32_t addr) {
    asm volatile("ldmatrix.sync.aligned.m8n8.x2.shared.b16 {%0,%1}, [%2];"
                 : "=r"(r[0]), "=r"(r[1]) : "r"(addr));
}
__device__ __forceinline__ void mma16816(float* d, const uint32_t* a, const uint32_t* b) {
    asm volatile(
        "mma.sync.aligned.m16n8k16.row.col.f32.bf16.bf16.f32 "
        "{%0,%1,%2,%3}, {%4,%5,%6,%7}, {%8,%9}, {%0,%1,%2,%3};"
        : "+f"(d[0]), "+f"(d[1]), "+f"(d[2]), "+f"(d[3])
        : "r"(a[0]), "r"(a[1]), "r"(a[2]), "r"(a[3]), "r"(b[0]), "r"(b[1]));
}

// ---------------- tensor-core GEMM via mma.sync ----------------
// C[M,Q] = A[M,64] @ B[Q,64]^T (+bias), B pre-split bf16 hi/lo, split-bf16 3 passes.
// grid = (ceil(M/128), Q/64); 256 threads = 8 warps in 4(M) x 2(N); warp tile 32x32.
// smem pitch 144B (72 bf16): conflict-free ldmatrix.
#define SP 144
#define SM_A_HI 0
#define SM_A_LO 18432
#define SM_B_HI 36864
#define SM_B_LO 46080
#define SM_TOTAL 55296

struct __align__(16) bf8 { __nv_bfloat16 v[8]; };

__global__ void __launch_bounds__(256)
gemm_mma(const float* __restrict__ A, const __nv_bfloat16* __restrict__ Bhi,
         const __nv_bfloat16* __restrict__ Blo, const float* __restrict__ bias,
         float* __restrict__ C, int M, int Q) {
    extern __shared__ __align__(16) char smem[];
    uint32_t sb = smem_u32(smem);
    int tid = threadIdx.x;
    int wid = tid >> 5, lane = tid & 31;
    int wm = wid & 3, wn = wid >> 2;
    int m0 = blockIdx.x * 128, q0 = blockIdx.y * 64;

    // load A tile: 128x64 fp32 -> bf16 hi/lo (1024 8-elem segments)
    for (int s = tid; s < 1024; s += 256) {
        int row = s >> 3, cs = s & 7;
        int gr = m0 + row;
        float f[8];
        if (gr < M) {
            float4 f0 = *(const float4*)(A + (size_t)gr * 64 + cs * 8);
            float4 f1 = *(const float4*)(A + (size_t)gr * 64 + cs * 8 + 4);
            f[0] = f0.x; f[1] = f0.y; f[2] = f0.z; f[3] = f0.w;
            f[4] = f1.x; f[5] = f1.y; f[6] = f1.z; f[7] = f1.w;
        } else {
#pragma unroll
            for (int i = 0; i < 8; i++) f[i] = 0.f;
        }
        bf8 hb, lb;
#pragma unroll
        for (int i = 0; i < 8; i++) {
            hb.v[i] = __float2bfloat16_rn(f[i]);
            lb.v[i] = __float2bfloat16_rn(f[i] - __bfloat162float(hb.v[i]));
        }
        *(uint4*)(smem + SM_A_HI + row * SP + cs * 16) = *(uint4*)&hb;
        *(uint4*)(smem + SM_A_LO + row * SP + cs * 16) = *(uint4*)&lb;
    }
    // load B tile: 64 rows x 64 bf16, pre-split (Q % 64 == 0, no bounds check)
    for (int s = tid; s < 512; s += 256) {
        int row = s >> 3, cs = s & 7;
        *(uint4*)(smem + SM_B_HI + row * SP + cs * 16) =
            *(const uint4*)(Bhi + (size_t)(q0 + row) * 64 + cs * 8);
        *(uint4*)(smem + SM_B_LO + row * SP + cs * 16) =
            *(const uint4*)(Blo + (size_t)(q0 + row) * 64 + cs * 8);
    }
    __syncthreads();

    float acc[2][4][4];
#pragma unroll
    for (int mi = 0; mi < 2; mi++)
#pragma unroll
        for (int ni = 0; ni < 4; ni++)
#pragma unroll
            for (int j = 0; j < 4; j++) acc[mi][ni][j] = 0.f;

    const int aoff[3] = {SM_A_HI, SM_A_HI, SM_A_LO};
    const int boff[3] = {SM_B_HI, SM_B_LO, SM_B_HI};

    // fragment address components
    int a_row = wm * 32 + (lane & 15);
    int a_kx = (lane >> 4) * 8;           // +8 cols for lanes 16-31
    int b_row = wn * 32 + (lane & 7);
    int b_kx = ((lane >> 3) & 1) * 8;     // lanes 8-15 -> k+8 (lanes>=16 ignored by x2)

#pragma unroll
    for (int pass = 0; pass < 3; pass++) {
        uint32_t abase = sb + aoff[pass];
        uint32_t bbase = sb + boff[pass];
#pragma unroll
        for (int ks = 0; ks < 4; ks++) {
            int k0 = ks * 16;
            uint32_t a[2][4];
#pragma unroll
            for (int mi = 0; mi < 2; mi++)
                ldsm4(a[mi], abase + (a_row + mi * 16) * SP + (k0 + a_kx) * 2);
            uint32_t b[4][2];
#pragma unroll
            for (int ni = 0; ni < 4; ni++)
                ldsm2(b[ni], bbase + (b_row + ni * 8) * SP + (k0 + b_kx) * 2);
#pragma unroll
            for (int mi = 0; mi < 2; mi++)
#pragma unroll
                for (int ni = 0; ni < 4; ni++)
                    mma16816(acc[mi][ni], a[mi], b[ni]);
        }
    }

    // epilogue: c0,c1 at (t/4, (t%4)*2), c2,c3 at (t/4+8, same cols)
    int mrow = lane >> 2;
    int mcol = (lane & 3) * 2;
#pragma unroll
    for (int mi = 0; mi < 2; mi++) {
        int r = m0 + wm * 32 + mi * 16 + mrow;
#pragma unroll
        for (int ni = 0; ni < 4; ni++) {
            int c = q0 + wn * 32 + ni * 8 + mcol;
            float bx = 0.f, by = 0.f;
            if (bias) { bx = bias[c]; by = bias[c + 1]; }
            if (r < M) {
                float2 v = {acc[mi][ni][0] + bx, acc[mi][ni][1] + by};
                *(float2*)(C + (size_t)r * Q + c) = v;
            }
            if (r + 8 < M) {
                float2 v = {acc[mi][ni][2] + bx, acc[mi][ni][3] + by};
                *(float2*)(C + (size_t)(r + 8) * Q + c) = v;
            }
        }
    }
}

// ---------------- weight pre-transpose + bf16 split ----------------
__global__ void wt_pack(const float* __restrict__ ee, const float* __restrict__ wih,
                        const float* __restrict__ whh,
                        __nv_bfloat16* __restrict__ whi, __nv_bfloat16* __restrict__ wlo) {
    int idx = blockIdx.x * blockDim.x + threadIdx.x;
    if (idx >= 704 * 64) return;
    int n = idx >> 6, k = idx & 63;
    float f;
    if (n < 320) f = ee[(n >> 6) * 4096 + k * 64 + (n & 63)];
    else if (n < 512) f = wih[k * 192 + (n - 320)];
    else f = whh[k * 192 + (n - 512)];
    __nv_bfloat16 hi = __float2bfloat16_rn(f);
    whi[idx] = hi;
    wlo[idx] = __float2bfloat16_rn(f - __bfloat162float(hi));
}

// ---------------- setup / graph kernels (R1-proven) ----------------
__global__ void zero_k(int* __restrict__ counts) {
    int i = blockIdx.x * blockDim.x + threadIdx.x;
    if (i < NN) counts[i] = 0;
}

__global__ void lin0_k(const float* __restrict__ x, const float* __restrict__ w,
                       const float* __restrict__ b, float* __restrict__ h,
                       float* __restrict__ out0) {
    __shared__ float ws[15 * 64];
    __shared__ float bs[64];
    for (int i = threadIdx.x; i < 15 * 64; i += blockDim.x) ws[i] = w[i];
    if (threadIdx.x < 64) bs[threadIdx.x] = b[threadIdx.x];
    __syncthreads();
    int idx = blockIdx.x * blockDim.x + threadIdx.x;
    if (idx >= NN * 64) return;
    int n = idx >> 6, j = idx & 63;
    float s = bs[j];
    const float* xr = x + n * 15;
#pragma unroll
    for (int k = 0; k < 15; k++) s += xr[k] * ws[k * 64 + j];
    s = fmaxf(s, 0.f);
    h[idx] = s;
    out0[idx] = s;
}

__global__ void hist_k(const int* __restrict__ dst, int* __restrict__ counts) {
    int e = blockIdx.x * blockDim.x + threadIdx.x;
    if (e < EE) atomicAdd(&counts[dst[e]], 1);
}

__global__ void scan1(const int* __restrict__ counts, int* __restrict__ rowoff,
                      int* __restrict__ bsums) {
    __shared__ int sm[1024];
    int b = blockIdx.x, t = threadIdx.x;
    int i = b * 1024 + t;
    int v = (i < NN) ? counts[i] : 0;
    sm[t] = v;
    __syncthreads();
    for (int off = 1; off < 1024; off <<= 1) {
        int xv = (t >= off) ? sm[t - off] : 0;
        __syncthreads();
        sm[t] += xv;
        __syncthreads();
    }
    if (i < NN) rowoff[i] = sm[t] - v;
    if (t == 1023) bsums[b] = sm[t];
}

__global__ void scan2(int* __restrict__ bsums, int* __restrict__ rowoff, int nb) {
    if (threadIdx.x == 0 && blockIdx.x == 0) {
        int run = 0;
        for (int b = 0; b < nb; b++) { int tv = bsums[b]; bsums[b] = run; run += tv; }
        rowoff[NN] = run;
    }
}

__global__ void scan3(int* __restrict__ rowoff, const int* __restrict__ bsums,
                      int* __restrict__ cursor) {
    int i = blockIdx.x * blockDim.x + threadIdx.x;
    if (i < NN) {
        int v = rowoff[i] + bsums[i >> 10];
        rowoff[i] = v;
        cursor[i] = v;
    }
}

__global__ void fill_k(const int* __restrict__ src, const int* __restrict__ dst,
                       const int* __restrict__ typ, int* __restrict__ cursor,
                       unsigned* __restrict__ sorted) {
    int e = blockIdx.x * blockDim.x + threadIdx.x;
    if (e < EE) {
        int p = atomicAdd(&cursor[dst[e]], 1);
        sorted[p] = (unsigned)src[e] | ((unsigned)typ[e] << 17);
    }
}

// one warp per dst node: m[n] = relu( (sum_e T[src_e, type_e]) / deg + conv_bias )
__global__ void agg_k(const unsigned* __restrict__ sorted, const int* __restrict__ rowoff,
                      const int* __restrict__ counts, const float* __restrict__ T,
                      const float* __restrict__ cbias, float* __restrict__ m) {
    int w = (int)((blockIdx.x * blockDim.x + threadIdx.x) >> 5);
    int lane = threadIdx.x & 31;
    if (w >= NN) return;
    int s = rowoff[w], e = rowoff[w + 1];
    const float2* T2 = (const float2*)T;
    float ax = 0.f, ay = 0.f;
    int i = s;
    for (; i + 2 <= e; i += 2) {
        unsigned m0v = sorted[i], m1v = sorted[i + 1];
        float2 v0 = T2[(m0v & 0x1FFFFu) * 160u + (m0v >> 17) * 32u + lane];
        float2 v1 = T2[(m1v & 0x1FFFFu) * 160u + (m1v >> 17) * 32u + lane];
        ax += v0.x + v1.x;
        ay += v0.y + v1.y;
    }
    if (i < e) {
        unsigned mv = sorted[i];
        float2 v = T2[(mv & 0x1FFFFu) * 160u + (mv >> 17) * 32u + lane];
        ax += v.x; ay += v.y;
    }
    float inv = 1.f / fmaxf((float)counts[w], 1.f);
    float2 b = ((const float2*)cbias)[lane];
    float2 o;
    o.x = fmaxf(ax * inv + b.x, 0.f);
    o.y = fmaxf(ay * inv + b.y, 0.f);
    ((float2*)m)[w * 32 + lane] = o;
}

__global__ void gru_k(const float* __restrict__ gx, const float* __restrict__ gh,
                      float* __restrict__ h) {
    int idx = blockIdx.x * blockDim.x + threadIdx.x;
    if (idx >= NN * 64) return;
    int n = idx >> 6, j = idx & 63;
    const float* px = gx + n * 192;
    const float* ph = gh + n * 192;
    float r = 1.f / (1.f + __expf(-(px[j] + ph[j])));
    float z = 1.f / (1.f + __expf(-(px[64 + j] + ph[64 + j])));
    float t = tanhf(px[128 + j] + r * ph[128 + j]);
    float hv = h[idx];
    h[idx] = (1.f - z) * t + z * hv;
}

__global__ void final_k(const float* __restrict__ I, const float* __restrict__ J,
                        const int* __restrict__ batch, float* __restrict__ out) {
    int idx = blockIdx.x * blockDim.x + threadIdx.x;
    if (idx >= NN * 12) return;
    int n = idx / 12;
    int j = idx - n * 12;
    atomicAdd(&out[batch[n] * 12 + j], I[idx] * J[idx]);
}

// ---------------- FFMA GEMM for readout (small) ----------------
__global__ void __launch_bounds__(256, 2)
gemm64(const float* __restrict__ A, const float* __restrict__ B,
       const float* __restrict__ bias, const float* __restrict__ Cin,
       float* __restrict__ C, int M, int Q, int act) {
    __shared__ float As[8][128];
    __shared__ float Bs[8][64];
    int tid = threadIdx.x;
    int tx = tid & 15, ty = tid >> 4;
    int m0 = blockIdx.y * 128, q0 = blockIdx.x * 64;

    float acc[8][4];
#pragma unroll
    for (int i = 0; i < 8; i++)
#pragma unroll
        for (int j = 0; j < 4; j++) acc[i][j] = 0.f;

    int arow = tid >> 1;
    int akoff = (tid & 1) * 4;

    for (int kc = 0; kc < 64; kc += 8) {
        float4 av = make_float4(0.f, 0.f, 0.f, 0.f);
        int gr = m0 + arow;
        if (gr < M) av = *(const float4*)(A + (size_t)gr * 64 + kc + akoff);
        As[akoff + 0][arow] = av.x;
        As[akoff + 1][arow] = av.y;
        As[akoff + 2][arow] = av.z;
        As[akoff + 3][arow] = av.w;
        if (tid < 128) {
            int k = tid >> 4;
            int qq = (tid & 15) * 4;
            float4 bv = make_float4(0.f, 0.f, 0.f, 0.f);
            if (q0 + qq < Q) bv = *(const float4*)(B + (size_t)(kc + k) * Q + q0 + qq);
            *(float4*)&Bs[k][qq] = bv;
        }
        __syncthreads();
#pragma unroll
        for (int k = 0; k < 8; k++) {
            float4 a0 = *(float4*)&As[k][ty * 8];
            float4 a1 = *(float4*)&As[k][ty * 8 + 4];
            float4 b = *(float4*)&Bs[k][tx * 4];
            float a[8] = {a0.x, a0.y, a0.z, a0.w, a1.x, a1.y, a1.z, a1.w};
#pragma unroll
            for (int i = 0; i < 8; i++) {
                acc[i][0] += a[i] * b.x;
                acc[i][1] += a[i] * b.y;
                acc[i][2] += a[i] * b.z;
                acc[i][3] += a[i] * b.w;
            }
        }
        __syncthreads();
    }

    int qc = q0 + tx * 4;
    if (qc >= Q) return;
    float4 bv = make_float4(0.f, 0.f, 0.f, 0.f);
    if (bias) bv = *(const float4*)(bias + qc);
#pragma unroll
    for (int i = 0; i < 8; i++) {
        int r = m0 + ty * 8 + i;
        if (r >= M) break;
        float4 v;
        v.x = acc[i][0] + bv.x;
        v.y = acc[i][1] + bv.y;
        v.z = acc[i][2] + bv.z;
        v.w = acc[i][3] + bv.w;
        if (Cin) {
            float4 c = *(const float4*)(Cin + (size_t)r * Q + qc);
            v.x += c.x; v.y += c.y; v.z += c.z; v.w += c.w;
        }
        if (act == 1) {
            v.x = fmaxf(v.x, 0.f); v.y = fmaxf(v.y, 0.f);
            v.z = fmaxf(v.z, 0.f); v.w = fmaxf(v.w, 0.f);
        } else if (act == 2) {
            v.x = 1.f / (1.f + __expf(-v.x));
            v.y = 1.f / (1.f + __expf(-v.y));
            v.z = 1.f / (1.f + __expf(-v.z));
            v.w = 1.f / (1.f + __expf(-v.w));
        }
        *(float4*)(C + (size_t)r * Q + qc) = v;
    }
}

// ---------------- launch ----------------
extern "C" void kernel_launch(void* const* d_in, const int* in_sizes, int n_in,
                              void* d_out, int out_size) {
    const float* x      = (const float*)d_in[0];
    const int*   ei     = (const int*)d_in[1];
    const int*   ea     = (const int*)d_in[2];
    const int*   batch  = (const int*)d_in[3];
    const float* lin0_w = (const float*)d_in[4];
    const float* lin0_b = (const float*)d_in[5];
    const float* ee     = (const float*)d_in[6];
    const float* cbias  = (const float*)d_in[7];
    const float* wih    = (const float*)d_in[8];
    const float* whh    = (const float*)d_in[9];
    const float* bih    = (const float*)d_in[10];
    const float* bhh    = (const float*)d_in[11];
    const float* iw1    = (const float*)d_in[12];
    const float* ib1    = (const float*)d_in[13];
    const float* iw2    = (const float*)d_in[14];
    const float* ib2    = (const float*)d_in[15];
    const float* jw1    = (const float*)d_in[16];
    const float* jb1    = (const float*)d_in[17];
    const float* jw2    = (const float*)d_in[18];
    const float* jb2    = (const float*)d_in[19];
    float* out = (float*)d_out;

    float *h, *out0, *T, *m, *gx, *gh, *A1, *I, *J;
    int *counts, *rowoff, *cursor, *bsums;
    unsigned* sorted;
    __nv_bfloat16 *wthi, *wtlo;
    cudaGetSymbolAddress((void**)&h, g_h);
    cudaGetSymbolAddress((void**)&out0, g_out0);
    cudaGetSymbolAddress((void**)&T, g_T);
    cudaGetSymbolAddress((void**)&m, g_m);
    cudaGetSymbolAddress((void**)&gx, g_gx);
    cudaGetSymbolAddress((void**)&gh, g_gh);
    cudaGetSymbolAddress((void**)&A1, g_A1);
    cudaGetSymbolAddress((void**)&I, g_I);
    cudaGetSymbolAddress((void**)&J, g_J);
    cudaGetSymbolAddress((void**)&counts, g_counts);
    cudaGetSymbolAddress((void**)&rowoff, g_rowoff);
    cudaGetSymbolAddress((void**)&cursor, g_cursor);
    cudaGetSymbolAddress((void**)&bsums, g_bsums);
    cudaGetSymbolAddress((void**)&sorted, g_sorted);
    cudaGetSymbolAddress((void**)&wthi, g_wthi);
    cudaGetSymbolAddress((void**)&wtlo, g_wtlo);

    cudaFuncSetAttribute(gemm_mma, cudaFuncAttributeMaxDynamicSharedMemorySize, SM_TOTAL);

    cudaStream_t s = 0;
    const int nb = (NN + 1023) / 1024;
    const int ntile = (NN + 127) / 128;

    zero_k<<<(NN + 255) / 256, 256, 0, s>>>(counts);
    wt_pack<<<(704 * 64 + 255) / 256, 256, 0, s>>>(ee, wih, whh, wthi, wtlo);
    lin0_k<<<(NN * 64 + 255) / 256, 256, 0, s>>>(x, lin0_w, lin0_b, h, out0);
    hist_k<<<(EE + 255) / 256, 256, 0, s>>>(ei + EE, counts);
    scan1<<<nb, 1024, 0, s>>>(counts, rowoff, bsums);
    scan2<<<1, 32, 0, s>>>(bsums, rowoff, nb);
    scan3<<<(NN + 255) / 256, 256, 0, s>>>(rowoff, bsums, cursor);
    fill_k<<<(EE + 255) / 256, 256, 0, s>>>(ei, ei + EE, ea, cursor, sorted);

    dim3 g1(1, (NN + 127) / 128);
    dim3 gridT(ntile, 5);   // Q=320
    dim3 gridG(ntile, 3);   // Q=192

    for (int step = 0; step < 6; step++) {
        gemm_mma<<<gridT, 256, SM_TOTAL, s>>>(h, wthi, wtlo, nullptr, T, NN, 320);
        agg_k<<<(NN * 32 + 255) / 256, 256, 0, s>>>(sorted, rowoff, counts, T, cbias, m);
        gemm_mma<<<gridG, 256, SM_TOTAL, s>>>(m, wthi + 320 * 64, wtlo + 320 * 64, bih, gx, NN, 192);
        gemm_mma<<<gridG, 256, SM_TOTAL, s>>>(h, wthi + 512 * 64, wtlo + 512 * 64, bhh, gh, NN, 192);
        gru_k<<<(NN * 64 + 255) / 256, 256, 0, s>>>(gx, gh, h);
    }

    // readout (FFMA path, small)
    gemm64<<<g1, 256, 0, s>>>(h, iw1, ib1, nullptr, A1, NN, 64, 0);
    gemm64<<<g1, 256, 0, s>>>(out0, iw1 + 64 * 64, nullptr, A1, A1, NN, 64, 2);
    gemm64<<<g1, 256, 0, s>>>(A1, iw2, ib2, nullptr, I, NN, 12, 2);
    gemm64<<<g1, 256, 0, s>>>(h, jw1, jb1, nullptr, m, NN, 64, 2);
    gemm64<<<g1, 256, 0, s>>>(m, jw2, jb2, nullptr, J, NN, 12, 0);

    cudaMemsetAsync(out, 0, GGB * DOUTC * sizeof(float), s);
    final_k<<<(NN * 12 + 255) / 256, 256, 0, s>>>(I, J, batch, out);
}

// round 5
// speedup vs baseline: 2.4160x; 1.0823x over previous
#include <cuda_runtime.h>
#include <cuda_bf16.h>
#include <cstdint>

#define NN 100000
#define EE 3200000
#define HH 64
#define GGB 256
#define DOUTC 12

// ---------------- scratch ----------------
__device__ float g_h[NN * HH];
__device__ float g_out0[NN * HH];
__device__ __nv_bfloat16 g_T[NN * 320];   // bf16: 64 MB, L2-resident
__device__ float g_m[NN * HH];
__device__ float g_gx[NN * 192];
__device__ float g_gh[NN * 192];
__device__ float g_A1[NN * HH];
__device__ float g_I[NN * DOUTC];
__device__ float g_J[NN * DOUTC];
__device__ int g_counts[NN];
__device__ int g_rowoff[NN + 1];
__device__ int g_cursor[NN];
__device__ int g_bsums[128];
__device__ unsigned g_sorted[EE];
// transposed + bf16-split weights:
// rows 0..319 Wc^T, 320..511 wih^T, 512..703 whh^T, 704..767 iw1a^T, 768..831 iw1b^T, 832..895 jw1^T
__device__ __nv_bfloat16 g_wthi[896 * 64];
__device__ __nv_bfloat16 g_wtlo[896 * 64];

// ---------------- mma.sync helpers ----------------
__device__ __forceinline__ uint32_t smem_u32(const void* p) {
    uint32_t a;
    asm("{ .reg .u64 t; cvta.to.shared.u64 t, %1; cvt.u32.u64 %0, t; }" : "=r"(a) : "l"(p));
    return a;
}
__device__ __forceinline__ void ldsm4(uint32_t* r, uint32_t addr) {
    asm volatile("ldmatrix.sync.aligned.m8n8.x4.shared.b16 {%0,%1,%2,%3}, [%4];"
                 : "=r"(r[0]), "=r"(r[1]), "=r"(r[2]), "=r"(r[3]) : "r"(addr));
}
__device__ __forceinline__ void ldsm2(uint32_t* r, uint32_t addr) {
    asm volatile("ldmatrix.sync.aligned.m8n8.x2.shared.b16 {%0,%1}, [%2];"
                 : "=r"(r[0]), "=r"(r[1]) : "r"(addr));
}
__device__ __forceinline__ void mma16816(float* d, const uint32_t* a, const uint32_t* b) {
    asm volatile(
        "mma.sync.aligned.m16n8k16.row.col.f32.bf16.bf16.f32 "
        "{%0,%1,%2,%3}, {%4,%5,%6,%7}, {%8,%9}, {%0,%1,%2,%3};"
        : "+f"(d[0]), "+f"(d[1]), "+f"(d[2]), "+f"(d[3])
        : "r"(a[0]), "r"(a[1]), "r"(a[2]), "r"(a[3]), "r"(b[0]), "r"(b[1]));
}

#define SP 144
#define SM_A_HI 0
#define SM_A_LO 18432
#define SM_B_HI 36864
#define SM_B_LO 46080
#define SM_TOTAL 55296

struct __align__(16) bf8 { __nv_bfloat16 v[8]; };

// mainloop shared by both GEMM variants: leaves acc[2][4][4] computed
#define GEMM_MMA_BODY(Apt)                                                            \
    extern __shared__ __align__(16) char smem[];                                      \
    uint32_t sb = smem_u32(smem);                                                     \
    int tid = threadIdx.x;                                                            \
    int wid = tid >> 5, lane = tid & 31;                                              \
    int wm = wid & 3, wn = wid >> 2;                                                  \
    int m0 = blockIdx.x * 128, q0 = blockIdx.y * 64;                                  \
    for (int sidx = tid; sidx < 1024; sidx += 256) {                                  \
        int row = sidx >> 3, cs = sidx & 7;                                           \
        int gr = m0 + row;                                                            \
        float f[8];                                                                   \
        if (gr < M) {                                                                 \
            float4 f0 = *(const float4*)(Apt + (size_t)gr * 64 + cs * 8);             \
            float4 f1 = *(const float4*)(Apt + (size_t)gr * 64 + cs * 8 + 4);         \
            f[0] = f0.x; f[1] = f0.y; f[2] = f0.z; f[3] = f0.w;                       \
            f[4] = f1.x; f[5] = f1.y; f[6] = f1.z; f[7] = f1.w;                       \
        } else {                                                                      \
            _Pragma("unroll") for (int i = 0; i < 8; i++) f[i] = 0.f;                 \
        }                                                                             \
        bf8 hb, lb;                                                                   \
        _Pragma("unroll") for (int i = 0; i < 8; i++) {                               \
            hb.v[i] = __float2bfloat16_rn(f[i]);                                      \
            lb.v[i] = __float2bfloat16_rn(f[i] - __bfloat162float(hb.v[i]));          \
        }                                                                             \
        *(uint4*)(smem + SM_A_HI + row * SP + cs * 16) = *(uint4*)&hb;                \
        *(uint4*)(smem + SM_A_LO + row * SP + cs * 16) = *(uint4*)&lb;                \
    }                                                                                 \
    for (int sidx = tid; sidx < 512; sidx += 256) {                                   \
        int row = sidx >> 3, cs = sidx & 7;                                           \
        *(uint4*)(smem + SM_B_HI + row * SP + cs * 16) =                              \
            *(const uint4*)(Bhi + (size_t)(q0 + row) * 64 + cs * 8);                  \
        *(uint4*)(smem + SM_B_LO + row * SP + cs * 16) =                              \
            *(const uint4*)(Blo + (size_t)(q0 + row) * 64 + cs * 8);                  \
    }                                                                                 \
    __syncthreads();                                                                  \
    float acc[2][4][4];                                                               \
    _Pragma("unroll") for (int mi = 0; mi < 2; mi++)                                  \
        _Pragma("unroll") for (int ni = 0; ni < 4; ni++)                              \
            _Pragma("unroll") for (int j = 0; j < 4; j++) acc[mi][ni][j] = 0.f;       \
    const int aoff[3] = {SM_A_HI, SM_A_HI, SM_A_LO};                                  \
    const int boff[3] = {SM_B_HI, SM_B_LO, SM_B_HI};                                  \
    int a_row = wm * 32 + (lane & 15);                                                \
    int a_kx = (lane >> 4) * 8;                                                       \
    int b_row = wn * 32 + (lane & 7);                                                 \
    int b_kx = ((lane >> 3) & 1) * 8;                                                 \
    _Pragma("unroll") for (int pass = 0; pass < 3; pass++) {                          \
        uint32_t abase = sb + aoff[pass];                                             \
        uint32_t bbase = sb + boff[pass];                                             \
        _Pragma("unroll") for (int ks = 0; ks < 4; ks++) {                            \
            int k0 = ks * 16;                                                         \
            uint32_t a[2][4];                                                         \
            _Pragma("unroll") for (int mi = 0; mi < 2; mi++)                          \
                ldsm4(a[mi], abase + (a_row + mi * 16) * SP + (k0 + a_kx) * 2);       \
            uint32_t b[4][2];                                                         \
            _Pragma("unroll") for (int ni = 0; ni < 4; ni++)                          \
                ldsm2(b[ni], bbase + (b_row + ni * 8) * SP + (k0 + b_kx) * 2);        \
            _Pragma("unroll") for (int mi = 0; mi < 2; mi++)                          \
                _Pragma("unroll") for (int ni = 0; ni < 4; ni++)                      \
                    mma16816(acc[mi][ni], a[mi], b[ni]);                              \
        }                                                                             \
    }                                                                                 \
    int mrow = lane >> 2;                                                             \
    int mcol = (lane & 3) * 2;

// fp32-out GEMM with bias / Cin-accumulate / activation (0 none, 2 sigmoid)
__global__ void __launch_bounds__(256)
gemm_mma(const float* __restrict__ A, const __nv_bfloat16* __restrict__ Bhi,
         const __nv_bfloat16* __restrict__ Blo, const float* __restrict__ bias,
         const float* __restrict__ Cin, float* __restrict__ C, int M, int Q, int act) {
    GEMM_MMA_BODY(A)
#pragma unroll
    for (int mi = 0; mi < 2; mi++) {
        int r = m0 + wm * 32 + mi * 16 + mrow;
#pragma unroll
        for (int ni = 0; ni < 4; ni++) {
            int c = q0 + wn * 32 + ni * 8 + mcol;
            float bx = 0.f, by = 0.f;
            if (bias) { bx = bias[c]; by = bias[c + 1]; }
#pragma unroll
            for (int hrow = 0; hrow < 2; hrow++) {
                int rr = r + hrow * 8;
                if (rr < M) {
                    float vx = acc[mi][ni][hrow * 2] + bx;
                    float vy = acc[mi][ni][hrow * 2 + 1] + by;
                    if (Cin) {
                        float2 ci = *(const float2*)(Cin + (size_t)rr * Q + c);
                        vx += ci.x; vy += ci.y;
                    }
                    if (act == 2) {
                        vx = 1.f / (1.f + __expf(-vx));
                        vy = 1.f / (1.f + __expf(-vy));
                    }
                    float2 v = {vx, vy};
                    *(float2*)(C + (size_t)rr * Q + c) = v;
                }
            }
        }
    }
}

// bf16-out GEMM (for T)
__global__ void __launch_bounds__(256)
gemm_mma_bf16(const float* __restrict__ A, const __nv_bfloat16* __restrict__ Bhi,
              const __nv_bfloat16* __restrict__ Blo, __nv_bfloat16* __restrict__ C,
              int M, int Q) {
    GEMM_MMA_BODY(A)
#pragma unroll
    for (int mi = 0; mi < 2; mi++) {
        int r = m0 + wm * 32 + mi * 16 + mrow;
#pragma unroll
        for (int ni = 0; ni < 4; ni++) {
            int c = q0 + wn * 32 + ni * 8 + mcol;
#pragma unroll
            for (int hrow = 0; hrow < 2; hrow++) {
                int rr = r + hrow * 8;
                if (rr < M) {
                    __nv_bfloat162 v;
                    v.x = __float2bfloat16_rn(acc[mi][ni][hrow * 2]);
                    v.y = __float2bfloat16_rn(acc[mi][ni][hrow * 2 + 1]);
                    *(__nv_bfloat162*)(C + (size_t)rr * Q + c) = v;
                }
            }
        }
    }
}

// ---------------- weight pre-transpose + bf16 split ----------------
__global__ void wt_pack(const float* __restrict__ ee, const float* __restrict__ wih,
                        const float* __restrict__ whh, const float* __restrict__ iw1,
                        const float* __restrict__ jw1,
                        __nv_bfloat16* __restrict__ whi, __nv_bfloat16* __restrict__ wlo) {
    int idx = blockIdx.x * blockDim.x + threadIdx.x;
    if (idx >= 896 * 64) return;
    int n = idx >> 6, k = idx & 63;
    float f;
    if (n < 320) f = ee[(n >> 6) * 4096 + k * 64 + (n & 63)];
    else if (n < 512) f = wih[k * 192 + (n - 320)];
    else if (n < 704) f = whh[k * 192 + (n - 512)];
    else if (n < 768) f = iw1[k * 64 + (n - 704)];
    else if (n < 832) f = iw1[(64 + k) * 64 + (n - 768)];
    else f = jw1[k * 64 + (n - 832)];
    __nv_bfloat16 hi = __float2bfloat16_rn(f);
    whi[idx] = hi;
    wlo[idx] = __float2bfloat16_rn(f - __bfloat162float(hi));
}

// ---------------- setup kernels (R1-proven) ----------------
__global__ void zero_k(int* __restrict__ counts) {
    int i = blockIdx.x * blockDim.x + threadIdx.x;
    if (i < NN) counts[i] = 0;
}

__global__ void lin0_k(const float* __restrict__ x, const float* __restrict__ w,
                       const float* __restrict__ b, float* __restrict__ h,
                       float* __restrict__ out0) {
    __shared__ float ws[15 * 64];
    __shared__ float bs[64];
    for (int i = threadIdx.x; i < 15 * 64; i += blockDim.x) ws[i] = w[i];
    if (threadIdx.x < 64) bs[threadIdx.x] = b[threadIdx.x];
    __syncthreads();
    int idx = blockIdx.x * blockDim.x + threadIdx.x;
    if (idx >= NN * 64) return;
    int n = idx >> 6, j = idx & 63;
    float s = bs[j];
    const float* xr = x + n * 15;
#pragma unroll
    for (int k = 0; k < 15; k++) s += xr[k] * ws[k * 64 + j];
    s = fmaxf(s, 0.f);
    h[idx] = s;
    out0[idx] = s;
}

__global__ void hist_k(const int* __restrict__ dst, int* __restrict__ counts) {
    int e = blockIdx.x * blockDim.x + threadIdx.x;
    if (e < EE) atomicAdd(&counts[dst[e]], 1);
}

__global__ void scan1(const int* __restrict__ counts, int* __restrict__ rowoff,
                      int* __restrict__ bsums) {
    __shared__ int sm[1024];
    int b = blockIdx.x, t = threadIdx.x;
    int i = b * 1024 + t;
    int v = (i < NN) ? counts[i] : 0;
    sm[t] = v;
    __syncthreads();
    for (int off = 1; off < 1024; off <<= 1) {
        int xv = (t >= off) ? sm[t - off] : 0;
        __syncthreads();
        sm[t] += xv;
        __syncthreads();
    }
    if (i < NN) rowoff[i] = sm[t] - v;
    if (t == 1023) bsums[b] = sm[t];
}

__global__ void scan2(int* __restrict__ bsums, int* __restrict__ rowoff, int nb) {
    if (threadIdx.x == 0 && blockIdx.x == 0) {
        int run = 0;
        for (int b = 0; b < nb; b++) { int tv = bsums[b]; bsums[b] = run; run += tv; }
        rowoff[NN] = run;
    }
}

__global__ void scan3(int* __restrict__ rowoff, const int* __restrict__ bsums,
                      int* __restrict__ cursor) {
    int i = blockIdx.x * blockDim.x + threadIdx.x;
    if (i < NN) {
        int v = rowoff[i] + bsums[i >> 10];
        rowoff[i] = v;
        cursor[i] = v;
    }
}

__global__ void fill_k(const int* __restrict__ src, const int* __restrict__ dst,
                       const int* __restrict__ typ, int* __restrict__ cursor,
                       unsigned* __restrict__ sorted) {
    int e = blockIdx.x * blockDim.x + threadIdx.x;
    if (e < EE) {
        int p = atomicAdd(&cursor[dst[e]], 1);
        sorted[p] = (unsigned)src[e] | ((unsigned)typ[e] << 17);
    }
}

// one warp per dst node; T is bf16 (row = 320 bf16 = 160 bf16x2)
__global__ void agg_k(const unsigned* __restrict__ sorted, const int* __restrict__ rowoff,
                      const int* __restrict__ counts, const __nv_bfloat162* __restrict__ T2,
                      const float* __restrict__ cbias, float* __restrict__ m) {
    int w = (int)((blockIdx.x * blockDim.x + threadIdx.x) >> 5);
    int lane = threadIdx.x & 31;
    if (w >= NN) return;
    int s = rowoff[w], e = rowoff[w + 1];
    float ax = 0.f, ay = 0.f;
    int i = s;
    for (; i + 2 <= e; i += 2) {
        unsigned v0 = sorted[i], v1 = sorted[i + 1];
        __nv_bfloat162 b0 = T2[(v0 & 0x1FFFFu) * 160u + (v0 >> 17) * 32u + lane];
        __nv_bfloat162 b1 = T2[(v1 & 0x1FFFFu) * 160u + (v1 >> 17) * 32u + lane];
        float2 f0 = __bfloat1622float2(b0);
        float2 f1 = __bfloat1622float2(b1);
        ax += f0.x + f1.x;
        ay += f0.y + f1.y;
    }
    if (i < e) {
        unsigned v0 = sorted[i];
        float2 f0 = __bfloat1622float2(T2[(v0 & 0x1FFFFu) * 160u + (v0 >> 17) * 32u + lane]);
        ax += f0.x; ay += f0.y;
    }
    float inv = 1.f / fmaxf((float)counts[w], 1.f);
    float2 b = ((const float2*)cbias)[lane];
    float2 o;
    o.x = fmaxf(ax * inv + b.x, 0.f);
    o.y = fmaxf(ay * inv + b.y, 0.f);
    ((float2*)m)[w * 32 + lane] = o;
}

__global__ void gru_k(const float* __restrict__ gx, const float* __restrict__ gh,
                      float* __restrict__ h) {
    int idx = blockIdx.x * blockDim.x + threadIdx.x;
    if (idx >= NN * 64) return;
    int n = idx >> 6, j = idx & 63;
    const float* px = gx + n * 192;
    const float* ph = gh + n * 192;
    float r = 1.f / (1.f + __expf(-(px[j] + ph[j])));
    float z = 1.f / (1.f + __expf(-(px[64 + j] + ph[64 + j])));
    float t = tanhf(px[128 + j] + r * ph[128 + j]);
    float hv = h[idx];
    h[idx] = (1.f - z) * t + z * hv;
}

__global__ void final_k(const float* __restrict__ I, const float* __restrict__ J,
                        const int* __restrict__ batch, float* __restrict__ out) {
    int idx = blockIdx.x * blockDim.x + threadIdx.x;
    if (idx >= NN * 12) return;
    int n = idx / 12;
    int j = idx - n * 12;
    atomicAdd(&out[batch[n] * 12 + j], I[idx] * J[idx]);
}

// ---------------- FFMA GEMM (only Q=12 readout tails) ----------------
__global__ void __launch_bounds__(256, 2)
gemm64(const float* __restrict__ A, const float* __restrict__ B,
       const float* __restrict__ bias, float* __restrict__ C, int M, int Q, int act) {
    __shared__ float As[8][128];
    __shared__ float Bs[8][64];
    int tid = threadIdx.x;
    int tx = tid & 15, ty = tid >> 4;
    int m0 = blockIdx.y * 128, q0 = blockIdx.x * 64;

    float acc[8][4];
#pragma unroll
    for (int i = 0; i < 8; i++)
#pragma unroll
        for (int j = 0; j < 4; j++) acc[i][j] = 0.f;

    int arow = tid >> 1;
    int akoff = (tid & 1) * 4;

    for (int kc = 0; kc < 64; kc += 8) {
        float4 av = make_float4(0.f, 0.f, 0.f, 0.f);
        int gr = m0 + arow;
        if (gr < M) av = *(const float4*)(A + (size_t)gr * 64 + kc + akoff);
        As[akoff + 0][arow] = av.x;
        As[akoff + 1][arow] = av.y;
        As[akoff + 2][arow] = av.z;
        As[akoff + 3][arow] = av.w;
        if (tid < 128) {
            int k = tid >> 4;
            int qq = (tid & 15) * 4;
            float4 bv = make_float4(0.f, 0.f, 0.f, 0.f);
            if (q0 + qq < Q) bv = *(const float4*)(B + (size_t)(kc + k) * Q + q0 + qq);
            *(float4*)&Bs[k][qq] = bv;
        }
        __syncthreads();
#pragma unroll
        for (int k = 0; k < 8; k++) {
            float4 a0 = *(float4*)&As[k][ty * 8];
            float4 a1 = *(float4*)&As[k][ty * 8 + 4];
            float4 b = *(float4*)&Bs[k][tx * 4];
            float a[8] = {a0.x, a0.y, a0.z, a0.w, a1.x, a1.y, a1.z, a1.w};
#pragma unroll
            for (int i = 0; i < 8; i++) {
                acc[i][0] += a[i] * b.x;
                acc[i][1] += a[i] * b.y;
                acc[i][2] += a[i] * b.z;
                acc[i][3] += a[i] * b.w;
            }
        }
        __syncthreads();
    }

    int qc = q0 + tx * 4;
    if (qc >= Q) return;
    float4 bv = make_float4(0.f, 0.f, 0.f, 0.f);
    if (bias) bv = *(const float4*)(bias + qc);
#pragma unroll
    for (int i = 0; i < 8; i++) {
        int r = m0 + ty * 8 + i;
        if (r >= M) break;
        float4 v;
        v.x = acc[i][0] + bv.x;
        v.y = acc[i][1] + bv.y;
        v.z = acc[i][2] + bv.z;
        v.w = acc[i][3] + bv.w;
        if (act == 2) {
            v.x = 1.f / (1.f + __expf(-v.x));
            v.y = 1.f / (1.f + __expf(-v.y));
            v.z = 1.f / (1.f + __expf(-v.z));
            v.w = 1.f / (1.f + __expf(-v.w));
        }
        *(float4*)(C + (size_t)r * Q + qc) = v;
    }
}

// ---------------- launch ----------------
extern "C" void kernel_launch(void* const* d_in, const int* in_sizes, int n_in,
                              void* d_out, int out_size) {
    const float* x      = (const float*)d_in[0];
    const int*   ei     = (const int*)d_in[1];
    const int*   ea     = (const int*)d_in[2];
    const int*   batch  = (const int*)d_in[3];
    const float* lin0_w = (const float*)d_in[4];
    const float* lin0_b = (const float*)d_in[5];
    const float* ee     = (const float*)d_in[6];
    const float* cbias  = (const float*)d_in[7];
    const float* wih    = (const float*)d_in[8];
    const float* whh    = (const float*)d_in[9];
    const float* bih    = (const float*)d_in[10];
    const float* bhh    = (const float*)d_in[11];
    const float* iw1    = (const float*)d_in[12];
    const float* ib1    = (const float*)d_in[13];
    const float* iw2    = (const float*)d_in[14];
    const float* ib2    = (const float*)d_in[15];
    const float* jw1    = (const float*)d_in[16];
    const float* jb1    = (const float*)d_in[17];
    const float* jw2    = (const float*)d_in[18];
    const float* jb2    = (const float*)d_in[19];
    float* out = (float*)d_out;

    float *h, *out0, *m, *gx, *gh, *A1, *I, *J;
    __nv_bfloat16* T;
    int *counts, *rowoff, *cursor, *bsums;
    unsigned* sorted;
    __nv_bfloat16 *wthi, *wtlo;
    cudaGetSymbolAddress((void**)&h, g_h);
    cudaGetSymbolAddress((void**)&out0, g_out0);
    cudaGetSymbolAddress((void**)&T, g_T);
    cudaGetSymbolAddress((void**)&m, g_m);
    cudaGetSymbolAddress((void**)&gx, g_gx);
    cudaGetSymbolAddress((void**)&gh, g_gh);
    cudaGetSymbolAddress((void**)&A1, g_A1);
    cudaGetSymbolAddress((void**)&I, g_I);
    cudaGetSymbolAddress((void**)&J, g_J);
    cudaGetSymbolAddress((void**)&counts, g_counts);
    cudaGetSymbolAddress((void**)&rowoff, g_rowoff);
    cudaGetSymbolAddress((void**)&cursor, g_cursor);
    cudaGetSymbolAddress((void**)&bsums, g_bsums);
    cudaGetSymbolAddress((void**)&sorted, g_sorted);
    cudaGetSymbolAddress((void**)&wthi, g_wthi);
    cudaGetSymbolAddress((void**)&wtlo, g_wtlo);

    cudaFuncSetAttribute(gemm_mma, cudaFuncAttributeMaxDynamicSharedMemorySize, SM_TOTAL);
    cudaFuncSetAttribute(gemm_mma_bf16, cudaFuncAttributeMaxDynamicSharedMemorySize, SM_TOTAL);

    cudaStream_t s = 0;
    const int nb = (NN + 1023) / 1024;
    const int ntile = (NN + 127) / 128;

    zero_k<<<(NN + 255) / 256, 256, 0, s>>>(counts);
    wt_pack<<<(896 * 64 + 255) / 256, 256, 0, s>>>(ee, wih, whh, iw1, jw1, wthi, wtlo);
    lin0_k<<<(NN * 64 + 255) / 256, 256, 0, s>>>(x, lin0_w, lin0_b, h, out0);
    hist_k<<<(EE + 255) / 256, 256, 0, s>>>(ei + EE, counts);
    scan1<<<nb, 1024, 0, s>>>(counts, rowoff, bsums);
    scan2<<<1, 32, 0, s>>>(bsums, rowoff, nb);
    scan3<<<(NN + 255) / 256, 256, 0, s>>>(rowoff, bsums, cursor);
    fill_k<<<(EE + 255) / 256, 256, 0, s>>>(ei, ei + EE, ea, cursor, sorted);

    dim3 gridT(ntile, 5);   // Q=320
    dim3 gridG(ntile, 3);   // Q=192
    dim3 grid1(ntile, 1);   // Q=64
    dim3 gr12(1, (NN + 127) / 128);

    for (int step = 0; step < 6; step++) {
        gemm_mma_bf16<<<gridT, 256, SM_TOTAL, s>>>(h, wthi, wtlo, T, NN, 320);
        agg_k<<<(NN * 32 + 255) / 256, 256, 0, s>>>(sorted, rowoff, counts,
                                                    (const __nv_bfloat162*)T, cbias, m);
        gemm_mma<<<gridG, 256, SM_TOTAL, s>>>(m, wthi + 320 * 64, wtlo + 320 * 64, bih,
                                              nullptr, gx, NN, 192, 0);
        gemm_mma<<<gridG, 256, SM_TOTAL, s>>>(h, wthi + 512 * 64, wtlo + 512 * 64, bhh,
                                              nullptr, gh, NN, 192, 0);
        gru_k<<<(NN * 64 + 255) / 256, 256, 0, s>>>(gx, gh, h);
    }

    // readout
    gemm_mma<<<grid1, 256, SM_TOTAL, s>>>(h, wthi + 704 * 64, wtlo + 704 * 64, ib1,
                                          nullptr, A1, NN, 64, 0);
    gemm_mma<<<grid1, 256, SM_TOTAL, s>>>(out0, wthi + 768 * 64, wtlo + 768 * 64, nullptr,
                                          A1, A1, NN, 64, 2);
    gemm64<<<gr12, 256, 0, s>>>(A1, iw2, ib2, I, NN, 12, 2);
    gemm_mma<<<grid1, 256, SM_TOTAL, s>>>(h, wthi + 832 * 64, wtlo + 832 * 64, jb1,
                                          nullptr, m, NN, 64, 2);
    gemm64<<<gr12, 256, 0, s>>>(m, jw2, jb2, J, NN, 12, 0);

    cudaMemsetAsync(out, 0, GGB * DOUTC * sizeof(float), s);
    final_k<<<(NN * 12 + 255) / 256, 256, 0, s>>>(I, J, batch, out);
}